// round 17
// baseline (speedup 1.0000x reference)
#include <cuda_runtime.h>
#include <cuda_fp16.h>
#include <float.h>
#include <stdint.h>

#define N_Q   4096
#define M_P   32768
#define W_F   768
#define K_NN  4
#define R2    0.25f
#define K_TOT (K_NN * W_F)        // 3072
#define IDX_SENT 0x7FFFFFFF

#define GRID_D 20                  // cells per axis (cell = 0.5 >= radius)
#define NCELL  (GRID_D * GRID_D * GRID_D)   // 8000

// ---------------- scratch (static device memory; no allocs allowed) --------
__device__ int      g_idx[N_Q * K_NN];
__device__ float    g_aggraw[N_Q * W_F];
__device__ int      g_cellcnt[NCELL];
__device__ int      g_cellfill[NCELL];
__device__ int      g_cellstart[NCELL + 1];
__device__ float4   g_binpts[M_P];       // binned {x,y,z,pp}
__device__ int      g_binidx[M_P];       // original point index
__device__ __half   g_B[(size_t)K_TOT * W_F];    // Wagg, fp16 [3072][768]

__device__ __forceinline__ bool pair_less(float d1, int i1, float d2, int i2) {
    return (d1 < d2) || (d1 == d2 && i1 < i2);
}

__device__ __forceinline__ uint32_t smem_u32(const void* p) {
    uint32_t a;
    asm("{ .reg .u64 t; cvta.to.shared.u64 t, %1; cvt.u32.u64 %0, t; }"
        : "=r"(a) : "l"(p));
    return a;
}

__device__ __forceinline__ int cell_of(float x, float y, float z) {
    int cx = (int)(x * 2.0f); cx = cx < 0 ? 0 : (cx > GRID_D - 1 ? GRID_D - 1 : cx);
    int cy = (int)(y * 2.0f); cy = cy < 0 ? 0 : (cy > GRID_D - 1 ? GRID_D - 1 : cy);
    int cz = (int)(z * 2.0f); cz = cz < 0 ? 0 : (cz > GRID_D - 1 ? GRID_D - 1 : cz);
    return cx + GRID_D * (cy + GRID_D * cz);
}

// ---------------------------------------------------------------------------
// Grid build: zero -> histogram -> scan (also zeroes fill) -> scatter
// ---------------------------------------------------------------------------
__global__ __launch_bounds__(256) void zero_kernel() {
    const int i = blockIdx.x * 256 + threadIdx.x;
    if (i < NCELL) g_cellcnt[i] = 0;
}

__global__ __launch_bounds__(256) void hist_kernel(const float* __restrict__ pts) {
    const int j = blockIdx.x * 256 + threadIdx.x;
    if (j < M_P) {
        const int c = cell_of(pts[j * 3 + 0], pts[j * 3 + 1], pts[j * 3 + 2]);
        atomicAdd(&g_cellcnt[c], 1);
    }
}

__global__ __launch_bounds__(1024) void scan_kernel() {
    __shared__ int part[1024];
    const int tid  = threadIdx.x;
    const int base = tid * 8;
    int pre[8];
    int sum = 0;
    #pragma unroll
    for (int i = 0; i < 8; i++) {
        const int idx = base + i;
        const int v = (idx < NCELL) ? g_cellcnt[idx] : 0;
        pre[i] = sum;
        sum += v;
    }
    part[tid] = sum;
    __syncthreads();
    for (int off = 1; off < 1024; off <<= 1) {
        int v = (tid >= off) ? part[tid - off] : 0;
        __syncthreads();
        part[tid] += v;
        __syncthreads();
    }
    const int offset = part[tid] - sum;
    #pragma unroll
    for (int i = 0; i < 8; i++) {
        const int idx = base + i;
        if (idx < NCELL) { g_cellstart[idx] = offset + pre[i]; g_cellfill[idx] = 0; }
    }
    if (tid == 1023) g_cellstart[NCELL] = part[1023];
}

__global__ __launch_bounds__(256) void scatter_kernel(const float* __restrict__ pts) {
    const int j = blockIdx.x * 256 + threadIdx.x;
    if (j < M_P) {
        const float px = pts[j * 3 + 0];
        const float py = pts[j * 3 + 1];
        const float pz = pts[j * 3 + 2];
        const float pp = __fmaf_rn(px, px, __fmaf_rn(py, py, __fmul_rn(pz, pz)));
        const int c = cell_of(px, py, pz);
        const int slot = g_cellstart[c] + atomicAdd(&g_cellfill[c], 1);
        g_binpts[slot] = make_float4(px, py, pz, pp);
        g_binidx[slot] = j;
    }
}

// ---------------------------------------------------------------------------
// Kernel 1: top-4 NN via grid — one thread per query. Arithmetic FROZEN.
// ---------------------------------------------------------------------------
__global__ __launch_bounds__(256) void topk_grid_kernel(const float* __restrict__ q_pos) {
    const int n = blockIdx.x * 256 + threadIdx.x;
    if (n >= N_Q) return;

    const float qx = q_pos[n * 3 + 0];
    const float qy = q_pos[n * 3 + 1];
    const float qz = q_pos[n * 3 + 2];
    const float qq = __fmaf_rn(qx, qx, __fmaf_rn(qy, qy, __fmul_rn(qz, qz)));

    int cx = (int)(qx * 2.0f); cx = cx < 0 ? 0 : (cx > GRID_D - 1 ? GRID_D - 1 : cx);
    int cy = (int)(qy * 2.0f); cy = cy < 0 ? 0 : (cy > GRID_D - 1 ? GRID_D - 1 : cy);
    int cz = (int)(qz * 2.0f); cz = cz < 0 ? 0 : (cz > GRID_D - 1 ? GRID_D - 1 : cz);

    const int xlo = cx > 0 ? cx - 1 : 0, xhi = cx < GRID_D - 1 ? cx + 1 : GRID_D - 1;
    const int ylo = cy > 0 ? cy - 1 : 0, yhi = cy < GRID_D - 1 ? cy + 1 : GRID_D - 1;
    const int zlo = cz > 0 ? cz - 1 : 0, zhi = cz < GRID_D - 1 ? cz + 1 : GRID_D - 1;

    float bd[4] = {R2, R2, R2, R2};
    int   bi[4] = {IDX_SENT, IDX_SENT, IDX_SENT, IDX_SENT};

    for (int z = zlo; z <= zhi; z++) {
        for (int y = ylo; y <= yhi; y++) {
            const int crow = GRID_D * (y + GRID_D * z);
            const int s0 = g_cellstart[crow + xlo];
            const int s1 = g_cellstart[crow + xhi + 1];
            for (int s = s0; s < s1; s++) {
                const float4 p = g_binpts[s];
                const int    j = g_binidx[s];
                float dot = __fmul_rn(qx, p.x);
                dot = __fmaf_rn(qy, p.y, dot);
                dot = __fmaf_rn(qz, p.z, dot);
                const float t1 = __fadd_rn(qq, p.w);
                const float d2 = __fadd_rn(t1, -__fmul_rn(2.0f, dot));
                if (d2 <= bd[3]) {
                    if (pair_less(d2, j, bd[3], bi[3])) {
                        bd[3] = d2; bi[3] = j;
                        #pragma unroll
                        for (int q = 3; q > 0; --q) {
                            if (pair_less(bd[q], bi[q], bd[q - 1], bi[q - 1])) {
                                float td = bd[q]; bd[q] = bd[q - 1]; bd[q - 1] = td;
                                int   ti = bi[q]; bi[q] = bi[q - 1]; bi[q - 1] = ti;
                            }
                        }
                    }
                }
            }
        }
    }

    #pragma unroll
    for (int k = 0; k < 4; k++)
        g_idx[n * 4 + k] = (bi[k] == IDX_SENT) ? -1 : bi[k];
}

// ---------------------------------------------------------------------------
// Kernel 2: convert Wagg[3072][768] -> g_B (fp16)
// ---------------------------------------------------------------------------
__global__ __launch_bounds__(256) void wconv_kernel(const float* __restrict__ Wagg) {
    const size_t id = (size_t)blockIdx.x * 256 + threadIdx.x;   // float4 index
    const float4 v = reinterpret_cast<const float4*>(Wagg)[id];
    __half2* ph = reinterpret_cast<__half2*>(g_B) + id * 2;
    ph[0] = __halves2half2(__float2half_rn(v.x), __float2half_rn(v.y));
    ph[1] = __halves2half2(__float2half_rn(v.z), __float2half_rn(v.w));
}

// ---------------------------------------------------------------------------
// Kernel 3: fp16 mma.sync GEMM with FUSED GATHER — C = A(feats[idx])·W.
// A tile loaded directly from fp32 feats via per-CTA idx table (smem),
// converted to fp16 in registers, STS into padded layout (zero rows for
// idx==-1 via zfill in registers). B via cp.async as before.
// CTA 128x64, K-tile 32, 8 warps, 3-stage, 3 CTAs/SM, single sync per iter.
// ---------------------------------------------------------------------------
#define CTA_M 128
#define CTA_N 64
#define CTA_K 32
#define STAGES 3
#define NKIT (K_TOT / CTA_K)                // 96
#define LDA_B 80
#define LDB_B 144
#define A_PLANE_B (CTA_M * LDA_B)           // 10240
#define B_PLANE_B (CTA_K * LDB_B)           // 4608
#define STAGE_B (A_PLANE_B + B_PLANE_B)     // 14848
#define GEMM_SMEM (STAGES * STAGE_B)        // 44544

#define CP_ASYNC16(saddr, gaddr) \
    asm volatile("cp.async.cg.shared.global [%0], [%1], 16;" :: "r"(saddr), "l"(gaddr))
#define CP_COMMIT()  asm volatile("cp.async.commit_group;" ::: "memory")
#define CP_WAIT(n)   asm volatile("cp.async.wait_group %0;" :: "n"(n) : "memory")

__device__ __forceinline__ void ldsm_x4(uint32_t& r0, uint32_t& r1, uint32_t& r2,
                                        uint32_t& r3, uint32_t addr) {
    asm volatile("ldmatrix.sync.aligned.m8n8.x4.shared.b16 {%0,%1,%2,%3}, [%4];"
                 : "=r"(r0), "=r"(r1), "=r"(r2), "=r"(r3) : "r"(addr));
}
__device__ __forceinline__ void ldsm_x4_t(uint32_t& r0, uint32_t& r1, uint32_t& r2,
                                          uint32_t& r3, uint32_t addr) {
    asm volatile("ldmatrix.sync.aligned.m8n8.x4.trans.shared.b16 {%0,%1,%2,%3}, [%4];"
                 : "=r"(r0), "=r"(r1), "=r"(r2), "=r"(r3) : "r"(addr));
}
__device__ __forceinline__ void mma16816_f16(float* c, const uint32_t* a, const uint32_t* b) {
    asm volatile(
        "mma.sync.aligned.m16n8k16.row.col.f32.f16.f16.f32 "
        "{%0,%1,%2,%3}, {%4,%5,%6,%7}, {%8,%9}, {%0,%1,%2,%3};"
        : "+f"(c[0]), "+f"(c[1]), "+f"(c[2]), "+f"(c[3])
        : "r"(a[0]), "r"(a[1]), "r"(a[2]), "r"(a[3]), "r"(b[0]), "r"(b[1]));
}

__device__ __forceinline__ uint32_t pack_h2(float x, float y) {
    const __half2 h = __halves2half2(__float2half_rn(x), __float2half_rn(y));
    return *reinterpret_cast<const uint32_t*>(&h);
}

// A gather+convert+STS (fp32 feats -> fp16 smem), B cp.async.
__device__ __forceinline__ void load_stage(char* smem, const float* __restrict__ feats,
                                           const int (*sidx)[4], int slot, int kt,
                                           int bn, int tid) {
    const uint32_t sbase = smem_u32(smem) + (uint32_t)slot * STAGE_B;
    const char* gB = reinterpret_cast<const char*>(g_B);

    // B first: 32 rows x 128B = 256 x 16B chunks; 1 per thread (async)
    {
        const int row = tid >> 3;
        const int col = (tid & 7) * 16;
        const size_t goff = ((size_t)(kt + row) * W_F + bn) * 2 + col;
        CP_ASYNC16(sbase + A_PLANE_B + row * LDB_B + col, gB + goff);
    }

    // A: 128 rows x 32 elems; thread -> (row, 16-elem segment)
    const int row  = tid >> 1;
    const int seg  = tid & 1;
    const int kidx = kt / W_F;
    const int wbase = kt - kidx * W_F;
    const int prow = sidx[row][kidx];
    float4 v0 = make_float4(0.f, 0.f, 0.f, 0.f), v1 = v0, v2 = v0, v3 = v0;
    if (prow >= 0) {
        const float4* src = reinterpret_cast<const float4*>(
            feats + (size_t)prow * W_F + wbase + seg * 16);
        v0 = src[0]; v1 = src[1]; v2 = src[2]; v3 = src[3];
    }
    uint4 u0, u1;
    u0.x = pack_h2(v0.x, v0.y); u0.y = pack_h2(v0.z, v0.w);
    u0.z = pack_h2(v1.x, v1.y); u0.w = pack_h2(v1.z, v1.w);
    u1.x = pack_h2(v2.x, v2.y); u1.y = pack_h2(v2.z, v2.w);
    u1.z = pack_h2(v3.x, v3.y); u1.w = pack_h2(v3.z, v3.w);
    char* adst = smem + (size_t)slot * STAGE_B + row * LDA_B + seg * 32;
    *reinterpret_cast<uint4*>(adst) = u0;
    *reinterpret_cast<uint4*>(adst + 16) = u1;
}

__global__ __launch_bounds__(256, 3) void gemm_mma_kernel(const float* __restrict__ feats,
                                                          const float* __restrict__ bagg) {
    extern __shared__ char smem[];
    __shared__ int sidx[CTA_M][4];
    const int tid  = threadIdx.x;
    const int wid  = tid >> 5;
    const int lane = tid & 31;
    const int bm = blockIdx.y * CTA_M;
    const int bn = blockIdx.x * CTA_N;
    const int wm = (wid & 3) * 32;
    const int wn = (wid >> 2) * 32;

    #pragma unroll
    for (int i = tid; i < CTA_M * 4; i += 256)
        (&sidx[0][0])[i] = g_idx[bm * 4 + i];
    __syncthreads();

    float c[2][4][4];
    #pragma unroll
    for (int mi = 0; mi < 2; mi++)
        #pragma unroll
        for (int ni = 0; ni < 4; ni++)
            #pragma unroll
            for (int r = 0; r < 4; r++) c[mi][ni][r] = 0.0f;

    load_stage(smem, feats, sidx, 0, 0, bn, tid); CP_COMMIT();
    load_stage(smem, feats, sidx, 1, CTA_K, bn, tid); CP_COMMIT();

    const uint32_t sb = smem_u32(smem);
    const int a_row = wm + (lane & 15);
    const int a_col = (lane >> 4) * 16;
    const int b_row = (lane & 7) + ((lane >> 3) & 1) * 8;
    const int b_col = wn + (lane >> 4) * 8;

    #pragma unroll 3
    for (int it = 0; it < NKIT; it++) {
        CP_WAIT(1);                 // stage 'it' B resident (A via sync below)
        __syncthreads();            // A STS of stage it visible; stage it-1 free

        if (it + 2 < NKIT)
            load_stage(smem, feats, sidx, (it + 2) % STAGES, (it + 2) * CTA_K, bn, tid);
        CP_COMMIT();

        const uint32_t st = sb + (uint32_t)(it % STAGES) * STAGE_B;
        const uint32_t sA = st;
        const uint32_t sB = st + A_PLANE_B;

        #pragma unroll
        for (int k16 = 0; k16 < 2; k16++) {
            uint32_t a[2][4];
            #pragma unroll
            for (int mi = 0; mi < 2; mi++) {
                const uint32_t off = (uint32_t)((a_row + mi * 16) * LDA_B
                                                + k16 * 32 + a_col);
                ldsm_x4(a[mi][0], a[mi][1], a[mi][2], a[mi][3], sA + off);
            }
            uint32_t b[4][2];
            #pragma unroll
            for (int nh = 0; nh < 2; nh++) {
                const uint32_t off = (uint32_t)((k16 * 16 + b_row) * LDB_B
                                                + (b_col + nh * 16) * 2);
                uint32_t r0, r1, r2, r3;
                ldsm_x4_t(r0, r1, r2, r3, sB + off);
                b[nh * 2 + 0][0] = r0; b[nh * 2 + 0][1] = r1;
                b[nh * 2 + 1][0] = r2; b[nh * 2 + 1][1] = r3;
            }
            #pragma unroll
            for (int mi = 0; mi < 2; mi++)
                #pragma unroll
                for (int ni = 0; ni < 4; ni++)
                    mma16816_f16(c[mi][ni], a[mi], b[ni]);
        }
    }

    #pragma unroll
    for (int mi = 0; mi < 2; mi++) {
        #pragma unroll
        for (int ni = 0; ni < 4; ni++) {
            const int row0 = bm + wm + mi * 16 + (lane >> 2);
            const int col  = bn + wn + ni * 8 + (lane & 3) * 2;
            const float bx = bagg[col], by = bagg[col + 1];
            float2 o0 = make_float2(c[mi][ni][0] + bx, c[mi][ni][1] + by);
            float2 o1 = make_float2(c[mi][ni][2] + bx, c[mi][ni][3] + by);
            *reinterpret_cast<float2*>(&g_aggraw[(size_t)row0 * W_F + col]) = o0;
            *reinterpret_cast<float2*>(&g_aggraw[(size_t)(row0 + 8) * W_F + col]) = o1;
        }
    }
}

// ---------------------------------------------------------------------------
// Kernel 4: warp-per-row pos GEMV + two LayerNorms + add. 8 rows per block.
// (R14 version — known good)
// ---------------------------------------------------------------------------
__global__ __launch_bounds__(256) void ln_kernel(const float* __restrict__ pos_in,
                                                 const float* __restrict__ Wpos,
                                                 const float* __restrict__ bpos,
                                                 const float* __restrict__ gagg,
                                                 const float* __restrict__ beagg,
                                                 const float* __restrict__ gpos,
                                                 const float* __restrict__ bepos,
                                                 float* __restrict__ out) {
    const int wid  = threadIdx.x >> 5;
    const int lane = threadIdx.x & 31;
    const int n    = blockIdx.x * 8 + wid;

    float pin[6];
    #pragma unroll
    for (int i = 0; i < 6; i++) pin[i] = pos_in[n * 6 + i];

    float a[24], p[24];
    float sa = 0.f, sp = 0.f;
    #pragma unroll
    for (int t = 0; t < 24; t++) {
        const int j = lane + t * 32;
        a[t] = g_aggraw[(size_t)n * W_F + j];
        float pv = bpos[j];
        #pragma unroll
        for (int i = 0; i < 6; i++) pv += pin[i] * Wpos[i * W_F + j];
        p[t] = pv;
        sa += a[t]; sp += p[t];
    }
    #pragma unroll
    for (int o = 16; o > 0; o >>= 1) {
        sa += __shfl_xor_sync(0xffffffffu, sa, o);
        sp += __shfl_xor_sync(0xffffffffu, sp, o);
    }
    const float ma = sa * (1.0f / 768.0f);
    const float mp = sp * (1.0f / 768.0f);

    float va = 0.f, vp = 0.f;
    #pragma unroll
    for (int t = 0; t < 24; t++) {
        const float da = a[t] - ma; va += da * da;
        const float dp = p[t] - mp; vp += dp * dp;
    }
    #pragma unroll
    for (int o = 16; o > 0; o >>= 1) {
        va += __shfl_xor_sync(0xffffffffu, va, o);
        vp += __shfl_xor_sync(0xffffffffu, vp, o);
    }
    const float inva = rsqrtf(va * (1.0f / 768.0f) + 1e-12f);
    const float invp = rsqrtf(vp * (1.0f / 768.0f) + 1e-12f);

    #pragma unroll
    for (int t = 0; t < 24; t++) {
        const int j = lane + t * 32;
        out[(size_t)n * W_F + j] = (a[t] - ma) * inva * gagg[j] + beagg[j]
                                 + (p[t] - mp) * invp * gpos[j] + bepos[j];
    }
}

// ---------------------------------------------------------------------------
extern "C" void kernel_launch(void* const* d_in, const int* in_sizes, int n_in,
                              void* d_out, int out_size) {
    const float* q_pos  = (const float*)d_in[0];
    const float* pts    = (const float*)d_in[1];
    const float* feats  = (const float*)d_in[2];
    const float* pos_in = (const float*)d_in[3];
    const float* Wagg   = (const float*)d_in[4];
    const float* bagg   = (const float*)d_in[5];
    const float* gagg   = (const float*)d_in[6];
    const float* beagg  = (const float*)d_in[7];
    const float* Wpos   = (const float*)d_in[8];
    const float* bpos   = (const float*)d_in[9];
    const float* gpos   = (const float*)d_in[10];
    const float* bepos  = (const float*)d_in[11];
    float* out = (float*)d_out;

    static int smem_set = 0;
    if (!smem_set) {
        cudaFuncSetAttribute(gemm_mma_kernel,
                             cudaFuncAttributeMaxDynamicSharedMemorySize, GEMM_SMEM);
        smem_set = 1;
    }

    // spatial-grid kNN path
    zero_kernel<<<(NCELL + 255) / 256, 256>>>();
    hist_kernel<<<(M_P + 255) / 256, 256>>>(pts);
    scan_kernel<<<1, 1024>>>();
    scatter_kernel<<<(M_P + 255) / 256, 256>>>(pts);
    topk_grid_kernel<<<(N_Q + 255) / 256, 256>>>(q_pos);

    wconv_kernel<<<(K_TOT * W_F / 4) / 256, 256>>>(Wagg);

    dim3 ggrid(W_F / CTA_N, N_Q / CTA_M);            // 12 x 32 = 384 CTAs
    gemm_mma_kernel<<<ggrid, 256, GEMM_SMEM>>>(feats, bagg);

    ln_kernel<<<N_Q / 8, 256>>>(pos_in, Wpos, bpos, gagg, beagg, gpos, bepos, out);
}